// round 12
// baseline (speedup 1.0000x reference)
#include <cuda_runtime.h>
#include <cstdint>

#define N_NODES 50000
#define N_RELS  50
#define N_CLASSES 10
#define EMB     16
#define RP      16
#define NT      300000
#define NRP     (N_NODES * RP)      // 800000
#define EPSV    1e-6f

// ---------------- scratch (static device globals; no allocation allowed) ----
__device__ float g_lat1[(size_t)NT * RP];     // 19.2 MB, layout [t][r]
__device__ float g_lat2[(size_t)NT * RP];     // 19.2 MB, layout [t][r]
__device__ float g_colsum[NRP];               // 3.2 MB
__device__ float g_rowsum[NRP];               // 3.2 MB
__device__ float g_h[N_NODES * EMB];          // 3.2 MB
__device__ float g_row0vec[EMB];              // unnormalized h2[0] (r=0 bulk)

// ---------------- init: zero scratch, logits = bias2 ------------------------
__global__ void k_init(const float* __restrict__ bias2, float* __restrict__ out) {
    int i = blockIdx.x * blockDim.x + threadIdx.x;
    int stride = gridDim.x * blockDim.x;
    for (int k = i; k < NRP; k += stride) {
        g_colsum[k] = 0.f;
        g_rowsum[k] = 0.f;
        g_h[k] = 0.f;                       // N_NODES*EMB == NRP
    }
    for (int k = i; k < N_NODES * N_CLASSES; k += stride)
        out[k] = bias2[k % N_CLASSES];
    if (i < EMB) g_row0vec[i] = 0.f;
}

// ---------------- latents: softmax(nhots@Wl + bl) for both layers -----------
// One half-warp (16 lanes) per triple t; lane index doubles as rp index.
// Also accumulates colsum/rowsum (r>=1 spread atomics; r==0 block-reduced).
__global__ void k_latent(const float* __restrict__ nhots,
                         const int*   __restrict__ hrow,   // s[t] = hrow[t]
                         const int*   __restrict__ vcol,   // o[t] = vcol[t]
                         const float* __restrict__ Wl1, const float* __restrict__ bl1,
                         const float* __restrict__ Wl2, const float* __restrict__ bl2) {
    __shared__ float sW1[N_RELS * RP], sW2[N_RELS * RP];
    __shared__ float sb1[RP], sb2[RP];
    __shared__ float sc0, sr0;
    for (int i = threadIdx.x; i < N_RELS * RP; i += blockDim.x) {
        sW1[i] = Wl1[i];
        sW2[i] = Wl2[i];
    }
    if (threadIdx.x < RP) { sb1[threadIdx.x] = bl1[threadIdx.x]; sb2[threadIdx.x] = bl2[threadIdx.x]; }
    if (threadIdx.x == 0) { sc0 = 0.f; sr0 = 0.f; }
    __syncthreads();

    const int lane = threadIdx.x & 15;
    const int hw   = (blockIdx.x * blockDim.x + threadIdx.x) >> 4;
    const int nhw  = (gridDim.x * blockDim.x) >> 4;

    float c0acc = 0.f, r0acc = 0.f;

    for (int t = hw; t < NT; t += nhw) {
        const float* nrow = nhots + (size_t)t * N_RELS;
        float a1 = sb1[lane], a2 = sb2[lane];
        #pragma unroll
        for (int base = 0; base < 48; base += 16) {
            float x = nrow[base + lane];
            #pragma unroll
            for (int rr = 0; rr < 16; rr++) {
                float v = __shfl_sync(0xffffffffu, x, rr, 16);
                a1 = fmaf(v, sW1[(base + rr) * RP + lane], a1);
                a2 = fmaf(v, sW2[(base + rr) * RP + lane], a2);
            }
        }
        {
            float x = (lane < 2) ? nrow[48 + lane] : 0.f;
            #pragma unroll
            for (int rr = 0; rr < 2; rr++) {
                float v = __shfl_sync(0xffffffffu, x, rr, 16);
                a1 = fmaf(v, sW1[(48 + rr) * RP + lane], a1);
                a2 = fmaf(v, sW2[(48 + rr) * RP + lane], a2);
            }
        }
        // softmax across the 16 lanes (both layers)
        float m1 = a1, m2 = a2;
        #pragma unroll
        for (int off = 8; off; off >>= 1) {
            m1 = fmaxf(m1, __shfl_xor_sync(0xffffffffu, m1, off, 16));
            m2 = fmaxf(m2, __shfl_xor_sync(0xffffffffu, m2, off, 16));
        }
        float e1 = __expf(a1 - m1), e2 = __expf(a2 - m2);
        float s1 = e1, s2 = e2;
        #pragma unroll
        for (int off = 8; off; off >>= 1) {
            s1 += __shfl_xor_sync(0xffffffffu, s1, off, 16);
            s2 += __shfl_xor_sync(0xffffffffu, s2, off, 16);
        }
        float l1 = e1 / s1;
        float l2 = e2 / s2;   // relu(softmax) == softmax (positive)

        g_lat1[(size_t)t * RP + lane] = l1;
        g_lat2[(size_t)t * RP + lane] = l2;

        int s = hrow[t];
        int o = vcol[t];
        if (lane == 0) {              // r=0: hcol==0, vrow==0 for every triple (hot)
            c0acc += l1;
            r0acc += l2;
        } else {
            atomicAdd(&g_colsum[o * lane], l1);
            atomicAdd(&g_rowsum[s * lane], l2);
        }
    }
    if (lane == 0) { atomicAdd(&sc0, c0acc); atomicAdd(&sr0, r0acc); }
    __syncthreads();
    if (threadIdx.x == 0) {
        atomicAdd(&g_colsum[0], sc0);
        atomicAdd(&g_rowsum[0], sr0);
    }
}

// ---------------- layer-1 SpMM: h[s] += sum_r lat1n[r,t] * W1flat[o*r] ------
// Half-warp per triple; the 16 r-copies share target row h[s[t]] -> one
// register-accumulated 16-vector, 16 atomics per triple instead of 256.
__global__ void k_h(const int* __restrict__ hrow, const int* __restrict__ vcol,
                    const float* __restrict__ w1) {
    const int lane = threadIdx.x & 15;
    const int hw   = (blockIdx.x * blockDim.x + threadIdx.x) >> 4;
    const int nhw  = (gridDim.x * blockDim.x) >> 4;

    for (int t = hw; t < NT; t += nhw) {
        int s = hrow[t];
        int o = vcol[t];
        float lv = g_lat1[(size_t)t * RP + lane];
        float cs = g_colsum[o * lane];           // lane == r here
        float ln = lv / fmaxf(cs, EPSV);
        float acc = 0.f;
        #pragma unroll
        for (int rr = 0; rr < 16; rr++) {
            float w = __shfl_sync(0xffffffffu, ln, rr, 16);
            acc = fmaf(w, w1[(size_t)(o * rr) * EMB + lane], acc);
        }
        atomicAdd(&g_h[s * EMB + lane], acc);
    }
}

// ---------------- h post: relu(h + bias1) -----------------------------------
__global__ void k_hpost(const float* __restrict__ bias1) {
    int i = blockIdx.x * blockDim.x + threadIdx.x;
    int stride = gridDim.x * blockDim.x;
    for (int k = i; k < N_NODES * EMB; k += stride)
        g_h[k] = fmaxf(g_h[k] + bias1[k & 15], 0.f);
}

// ---------------- layer-2 fused into logits ---------------------------------
// Half-warp per triple. Lane doubles as (r) for the scatter and (j) for the
// h[o] vector. r>=1: v = s*r -> logits[v % n] += lat2n * (h[o] . W2[v / n]).
// r==0 bulk handled as a register-accumulated reduction into g_row0vec.
__global__ void k_scatter(const int* __restrict__ hrow, const int* __restrict__ vcol,
                          const float* __restrict__ w2, float* __restrict__ logits) {
    __shared__ float sW2[RP * 161 + 160];    // stride 161 (coprime-ish to 32 banks)
    __shared__ float sred[EMB];
    for (int i = threadIdx.x; i < RP * EMB * N_CLASSES; i += blockDim.x) {
        int r = i / (EMB * N_CLASSES);
        int rem = i - r * (EMB * N_CLASSES);
        sW2[r * 161 + rem] = w2[i];
    }
    if (threadIdx.x < EMB) sred[threadIdx.x] = 0.f;
    __syncthreads();

    const int lane = threadIdx.x & 15;
    const int hw   = (blockIdx.x * blockDim.x + threadIdx.x) >> 4;
    const int nhw  = (gridDim.x * blockDim.x) >> 4;

    float part = 0.f;    // r=0 partial of h2-row-0[lane]

    for (int t = hw; t < NT; t += nhw) {
        int s = hrow[t];
        int o = vcol[t];
        float hv = g_h[o * EMB + lane];                // h[o][j=lane]
        float lv = g_lat2[(size_t)t * RP + lane];      // lat2[t][r=lane]
        float l20 = __shfl_sync(0xffffffffu, lv, 0, 16);
        part = fmaf(l20, hv, part);

        int v = s * lane;                              // 0 for lane 0 (safe dummy)
        float rs = g_rowsum[v];
        float ln = lv / fmaxf(rs, EPSV);
        int rprime = v / N_NODES;
        int node = v - rprime * N_NODES;
        const float* wrow = &sW2[rprime * 161];

        float acc[N_CLASSES];
        #pragma unroll
        for (int c = 0; c < N_CLASSES; c++) acc[c] = 0.f;
        #pragma unroll
        for (int j = 0; j < 16; j++) {
            float hj = __shfl_sync(0xffffffffu, hv, j, 16);
            #pragma unroll
            for (int c = 0; c < N_CLASSES; c++)
                acc[c] = fmaf(hj, wrow[j * N_CLASSES + c], acc[c]);
        }
        if (lane != 0) {
            float* lp = logits + (size_t)node * N_CLASSES;
            #pragma unroll
            for (int c = 0; c < N_CLASSES; c++)
                atomicAdd(lp + c, ln * acc[c]);
        }
    }
    atomicAdd(&sred[lane], part);
    __syncthreads();
    if (threadIdx.x < EMB) atomicAdd(&g_row0vec[threadIdx.x], sred[threadIdx.x]);
}

// ---------------- epilogue: r=0 contribution to logits[0] -------------------
__global__ void k_finish(const float* __restrict__ w2, float* __restrict__ logits) {
    if (threadIdx.x < N_CLASSES) {
        float denom = fmaxf(g_rowsum[0], EPSV);
        float acc = 0.f;
        #pragma unroll
        for (int j = 0; j < EMB; j++)
            acc = fmaf(w2[j * N_CLASSES + threadIdx.x], g_row0vec[j] / denom, acc);
        atomicAdd(&logits[threadIdx.x], acc);
    }
}

// ---------------- launch -----------------------------------------------------
extern "C" void kernel_launch(void* const* d_in, const int* in_sizes, int n_in,
                              void* d_out, int out_size) {
    const float* nhots    = (const float*)d_in[0];
    const int*   hrow     = (const int*)  d_in[1];
    // d_in[2] = hcol, d_in[3] = vrow  (derivable: hcol = o*r, vrow = s*r)
    const int*   vcol     = (const int*)  d_in[4];
    const float* Wl1      = (const float*)d_in[5];
    const float* bl1      = (const float*)d_in[6];
    const float* Wl2      = (const float*)d_in[7];
    const float* bl2      = (const float*)d_in[8];
    const float* weights1 = (const float*)d_in[9];
    const float* bias1    = (const float*)d_in[10];
    const float* weights2 = (const float*)d_in[11];
    const float* bias2    = (const float*)d_in[12];
    float* out = (float*)d_out;

    const int T = 256;
    k_init<<<1024, T>>>(bias2, out);
    k_latent<<<1184, T>>>(nhots, hrow, vcol, Wl1, bl1, Wl2, bl2);
    k_h<<<1184, T>>>(hrow, vcol, weights1);
    k_hpost<<<512, T>>>(bias1);
    k_scatter<<<1184, T>>>(hrow, vcol, weights2, out);
    k_finish<<<1, 32>>>(weights2, out);
}

// round 13
// speedup vs baseline: 1.0182x; 1.0182x over previous
#include <cuda_runtime.h>
#include <cstdint>

#define N_NODES 50000
#define N_RELS  50
#define N_CLASSES 10
#define EMB     16
#define RP      16
#define NT      300000
#define NRP     (N_NODES * RP)      // 800000
#define EPSV    1e-6f

// ---------------- scratch (static device globals; no allocation allowed) ----
__device__ float g_lat1[(size_t)NT * RP];     // 19.2 MB, layout [t][r]
__device__ float g_lat2[(size_t)NT * RP];     // 19.2 MB, layout [t][r]
__device__ float g_colsum[NRP];               // 3.2 MB
__device__ float g_rowsum[NRP];               // 3.2 MB
__device__ float g_h[N_NODES * EMB];          // 3.2 MB
__device__ float g_row0vec[EMB];              // unnormalized h2[0] (r=0 bulk)

// ---------------- init: zero scratch, logits = bias2 ------------------------
__global__ void k_init(const float* __restrict__ bias2, float* __restrict__ out) {
    int i = blockIdx.x * blockDim.x + threadIdx.x;
    int stride = gridDim.x * blockDim.x;
    for (int k = i; k < NRP; k += stride) {
        g_colsum[k] = 0.f;
        g_rowsum[k] = 0.f;
        g_h[k] = 0.f;                       // N_NODES*EMB == NRP
    }
    for (int k = i; k < N_NODES * N_CLASSES; k += stride)
        out[k] = bias2[k % N_CLASSES];
    if (i < EMB) g_row0vec[i] = 0.f;
}

// ---------------- latents: softmax(nhots@Wl + bl) for both layers -----------
// One half-warp (16 lanes) per triple t; lane index doubles as rp index.
// Also accumulates colsum/rowsum (r>=1 spread atomics; r==0 block-reduced).
__global__ void k_latent(const float* __restrict__ nhots,
                         const int*   __restrict__ hrow,   // s[t] = hrow[t]
                         const int*   __restrict__ vcol,   // o[t] = vcol[t]
                         const float* __restrict__ Wl1, const float* __restrict__ bl1,
                         const float* __restrict__ Wl2, const float* __restrict__ bl2) {
    __shared__ float sW1[N_RELS * RP], sW2[N_RELS * RP];
    __shared__ float sb1[RP], sb2[RP];
    __shared__ float sc0, sr0;
    for (int i = threadIdx.x; i < N_RELS * RP; i += blockDim.x) {
        sW1[i] = Wl1[i];
        sW2[i] = Wl2[i];
    }
    if (threadIdx.x < RP) { sb1[threadIdx.x] = bl1[threadIdx.x]; sb2[threadIdx.x] = bl2[threadIdx.x]; }
    if (threadIdx.x == 0) { sc0 = 0.f; sr0 = 0.f; }
    __syncthreads();

    const int lane = threadIdx.x & 15;
    const int hw   = (blockIdx.x * blockDim.x + threadIdx.x) >> 4;
    const int nhw  = (gridDim.x * blockDim.x) >> 4;

    float c0acc = 0.f, r0acc = 0.f;

    for (int t = hw; t < NT; t += nhw) {
        const float* nrow = nhots + (size_t)t * N_RELS;
        float a1 = sb1[lane], a2 = sb2[lane];
        #pragma unroll
        for (int base = 0; base < 48; base += 16) {
            float x = nrow[base + lane];
            #pragma unroll
            for (int rr = 0; rr < 16; rr++) {
                float v = __shfl_sync(0xffffffffu, x, rr, 16);
                a1 = fmaf(v, sW1[(base + rr) * RP + lane], a1);
                a2 = fmaf(v, sW2[(base + rr) * RP + lane], a2);
            }
        }
        {
            float x = (lane < 2) ? nrow[48 + lane] : 0.f;
            #pragma unroll
            for (int rr = 0; rr < 2; rr++) {
                float v = __shfl_sync(0xffffffffu, x, rr, 16);
                a1 = fmaf(v, sW1[(48 + rr) * RP + lane], a1);
                a2 = fmaf(v, sW2[(48 + rr) * RP + lane], a2);
            }
        }
        // softmax across the 16 lanes (both layers)
        float m1 = a1, m2 = a2;
        #pragma unroll
        for (int off = 8; off; off >>= 1) {
            m1 = fmaxf(m1, __shfl_xor_sync(0xffffffffu, m1, off, 16));
            m2 = fmaxf(m2, __shfl_xor_sync(0xffffffffu, m2, off, 16));
        }
        float e1 = __expf(a1 - m1), e2 = __expf(a2 - m2);
        float s1 = e1, s2 = e2;
        #pragma unroll
        for (int off = 8; off; off >>= 1) {
            s1 += __shfl_xor_sync(0xffffffffu, s1, off, 16);
            s2 += __shfl_xor_sync(0xffffffffu, s2, off, 16);
        }
        float l1 = e1 / s1;
        float l2 = e2 / s2;   // relu(softmax) == softmax (positive)

        g_lat1[(size_t)t * RP + lane] = l1;
        g_lat2[(size_t)t * RP + lane] = l2;

        int s = hrow[t];
        int o = vcol[t];
        if (lane == 0) {              // r=0: hcol==0, vrow==0 for every triple (hot)
            c0acc += l1;
            r0acc += l2;
        } else {
            atomicAdd(&g_colsum[o * lane], l1);
            atomicAdd(&g_rowsum[s * lane], l2);
        }
    }
    if (lane == 0) { atomicAdd(&sc0, c0acc); atomicAdd(&sr0, r0acc); }
    __syncthreads();
    if (threadIdx.x == 0) {
        atomicAdd(&g_colsum[0], sc0);
        atomicAdd(&g_rowsum[0], sr0);
    }
}

// ---------------- layer-1 SpMM: h[s] += sum_r lat1n[r,t] * W1flat[o*r] ------
// Half-warp per triple; the 16 r-copies share target row h[s[t]] -> one
// register-accumulated 16-vector, 16 atomics per triple instead of 256.
__global__ void k_h(const int* __restrict__ hrow, const int* __restrict__ vcol,
                    const float* __restrict__ w1) {
    const int lane = threadIdx.x & 15;
    const int hw   = (blockIdx.x * blockDim.x + threadIdx.x) >> 4;
    const int nhw  = (gridDim.x * blockDim.x) >> 4;

    for (int t = hw; t < NT; t += nhw) {
        int s = hrow[t];
        int o = vcol[t];
        float lv = g_lat1[(size_t)t * RP + lane];
        float cs = g_colsum[o * lane];           // lane == r here
        float ln = lv / fmaxf(cs, EPSV);
        float acc = 0.f;
        #pragma unroll
        for (int rr = 0; rr < 16; rr++) {
            float w = __shfl_sync(0xffffffffu, ln, rr, 16);
            acc = fmaf(w, w1[(size_t)(o * rr) * EMB + lane], acc);
        }
        atomicAdd(&g_h[s * EMB + lane], acc);
    }
}

// ---------------- h post: relu(h + bias1) -----------------------------------
__global__ void k_hpost(const float* __restrict__ bias1) {
    int i = blockIdx.x * blockDim.x + threadIdx.x;
    int stride = gridDim.x * blockDim.x;
    for (int k = i; k < N_NODES * EMB; k += stride)
        g_h[k] = fmaxf(g_h[k] + bias1[k & 15], 0.f);
}

// ---------------- layer-2 fused into logits ---------------------------------
// Half-warp per triple. Lane doubles as (r) for the scatter and (j) for the
// h[o] vector. r>=1: v = s*r -> logits[v % n] += lat2n * (h[o] . W2[v / n]).
// r==0 bulk handled as a register-accumulated reduction into g_row0vec.
__global__ void k_scatter(const int* __restrict__ hrow, const int* __restrict__ vcol,
                          const float* __restrict__ w2, float* __restrict__ logits) {
    __shared__ float sW2[RP * 161 + 160];    // stride 161 (coprime-ish to 32 banks)
    __shared__ float sred[EMB];
    for (int i = threadIdx.x; i < RP * EMB * N_CLASSES; i += blockDim.x) {
        int r = i / (EMB * N_CLASSES);
        int rem = i - r * (EMB * N_CLASSES);
        sW2[r * 161 + rem] = w2[i];
    }
    if (threadIdx.x < EMB) sred[threadIdx.x] = 0.f;
    __syncthreads();

    const int lane = threadIdx.x & 15;
    const int hw   = (blockIdx.x * blockDim.x + threadIdx.x) >> 4;
    const int nhw  = (gridDim.x * blockDim.x) >> 4;

    float part = 0.f;    // r=0 partial of h2-row-0[lane]

    for (int t = hw; t < NT; t += nhw) {
        int s = hrow[t];
        int o = vcol[t];
        float hv = g_h[o * EMB + lane];                // h[o][j=lane]
        float lv = g_lat2[(size_t)t * RP + lane];      // lat2[t][r=lane]
        float l20 = __shfl_sync(0xffffffffu, lv, 0, 16);
        part = fmaf(l20, hv, part);

        int v = s * lane;                              // 0 for lane 0 (safe dummy)
        float rs = g_rowsum[v];
        float ln = lv / fmaxf(rs, EPSV);
        int rprime = v / N_NODES;
        int node = v - rprime * N_NODES;
        const float* wrow = &sW2[rprime * 161];

        float acc[N_CLASSES];
        #pragma unroll
        for (int c = 0; c < N_CLASSES; c++) acc[c] = 0.f;
        #pragma unroll
        for (int j = 0; j < 16; j++) {
            float hj = __shfl_sync(0xffffffffu, hv, j, 16);
            #pragma unroll
            for (int c = 0; c < N_CLASSES; c++)
                acc[c] = fmaf(hj, wrow[j * N_CLASSES + c], acc[c]);
        }
        if (lane != 0) {
            float* lp = logits + (size_t)node * N_CLASSES;
            #pragma unroll
            for (int c = 0; c < N_CLASSES; c++)
                atomicAdd(lp + c, ln * acc[c]);
        }
    }
    atomicAdd(&sred[lane], part);
    __syncthreads();
    if (threadIdx.x < EMB) atomicAdd(&g_row0vec[threadIdx.x], sred[threadIdx.x]);
}

// ---------------- epilogue: r=0 contribution to logits[0] -------------------
__global__ void k_finish(const float* __restrict__ w2, float* __restrict__ logits) {
    if (threadIdx.x < N_CLASSES) {
        float denom = fmaxf(g_rowsum[0], EPSV);
        float acc = 0.f;
        #pragma unroll
        for (int j = 0; j < EMB; j++)
            acc = fmaf(w2[j * N_CLASSES + threadIdx.x], g_row0vec[j] / denom, acc);
        atomicAdd(&logits[threadIdx.x], acc);
    }
}

// ---------------- launch -----------------------------------------------------
extern "C" void kernel_launch(void* const* d_in, const int* in_sizes, int n_in,
                              void* d_out, int out_size) {
    const float* nhots    = (const float*)d_in[0];
    const int*   hrow     = (const int*)  d_in[1];
    // d_in[2] = hcol, d_in[3] = vrow  (derivable: hcol = o*r, vrow = s*r)
    const int*   vcol     = (const int*)  d_in[4];
    const float* Wl1      = (const float*)d_in[5];
    const float* bl1      = (const float*)d_in[6];
    const float* Wl2      = (const float*)d_in[7];
    const float* bl2      = (const float*)d_in[8];
    const float* weights1 = (const float*)d_in[9];
    const float* bias1    = (const float*)d_in[10];
    const float* weights2 = (const float*)d_in[11];
    const float* bias2    = (const float*)d_in[12];
    float* out = (float*)d_out;

    const int T = 256;
    k_init<<<1024, T>>>(bias2, out);
    k_latent<<<1184, T>>>(nhots, hrow, vcol, Wl1, bl1, Wl2, bl2);
    k_h<<<1184, T>>>(hrow, vcol, weights1);
    k_hpost<<<512, T>>>(bias1);
    k_scatter<<<1184, T>>>(hrow, vcol, weights2, out);
    k_finish<<<1, 32>>>(weights2, out);
}

// round 14
// speedup vs baseline: 1.8031x; 1.7708x over previous
#include <cuda_runtime.h>
#include <cstdint>

#define N_NODES 50000
#define N_RELS  50
#define N_CLASSES 10
#define EMB     16
#define RP      16
#define NT      300000
#define NRP     (N_NODES * RP)      // 800000
#define EPSV    1e-6f

// ---------------- scratch (static device globals) ---------------------------
__device__ float g_colsum[NRP];               // 3.2 MB (flat o*r segment sums)
__device__ float g_rowsum[NRP];               // 3.2 MB (flat s*r segment sums)
__device__ float g_h[N_NODES * EMB];          // 3.2 MB
__device__ float g_row0vec[EMB];              // unnormalized h2[0] (r=0 bulk)
__device__ float g_S1[N_RELS * RP];           // softmax(Wl1[p]+bl1) per relation
__device__ float g_S2[N_RELS * RP];
__device__ int   g_p[NT];                     // relation id per triple
__device__ int   g_idx[NT];                   // CSR-by-s triple list
__device__ int   g_cnt[N_NODES];
__device__ int   g_start[N_NODES + 1];
__device__ int   g_cur[N_NODES];

// ---------------- init: zero scratch, logits = bias2 ------------------------
__global__ void k_init(const float* __restrict__ bias2, float* __restrict__ out) {
    int i = blockIdx.x * blockDim.x + threadIdx.x;
    int stride = gridDim.x * blockDim.x;
    for (int k = i; k < NRP; k += stride) {
        g_colsum[k] = 0.f;
        g_rowsum[k] = 0.f;
        g_h[k] = 0.f;                          // N_NODES*EMB == NRP
    }
    for (int k = i; k < N_NODES; k += stride) g_cnt[k] = 0;
    for (int k = i; k < N_NODES * N_CLASSES; k += stride)
        out[k] = bias2[k % N_CLASSES];
    if (i < EMB) g_row0vec[i] = 0.f;
}

// ---------------- per-relation softmax tables (50 x 16, both layers) --------
__global__ void k_soft(const float* __restrict__ Wl1, const float* __restrict__ bl1,
                       const float* __restrict__ Wl2, const float* __restrict__ bl2) {
    int lane = threadIdx.x & 15;
    int hw = threadIdx.x >> 4;                 // 32 half-warps
    unsigned hm = 0xFFFFu << (threadIdx.x & 16);
    for (int row = hw; row < N_RELS; row += 32) {
        float a1 = Wl1[row * RP + lane] + bl1[lane];
        float a2 = Wl2[row * RP + lane] + bl2[lane];
        float m1 = a1, m2 = a2;
        #pragma unroll
        for (int off = 8; off; off >>= 1) {
            m1 = fmaxf(m1, __shfl_xor_sync(hm, m1, off, 16));
            m2 = fmaxf(m2, __shfl_xor_sync(hm, m2, off, 16));
        }
        float e1 = __expf(a1 - m1), e2 = __expf(a2 - m2);
        float s1 = e1, s2 = e2;
        #pragma unroll
        for (int off = 8; off; off >>= 1) {
            s1 += __shfl_xor_sync(hm, s1, off, 16);
            s2 += __shfl_xor_sync(hm, s2, off, 16);
        }
        g_S1[row * RP + lane] = e1 / s1;
        g_S2[row * RP + lane] = e2 / s2;       // relu(softmax) == softmax
    }
}

// ---------------- find p[t] from one-hot, counts, colsum/rowsum atomics -----
// One half-warp per triple. Exact grid: NT*16/256 = 18750 blocks.
__global__ void k_p(const float* __restrict__ nhots,
                    const int* __restrict__ hrow, const int* __restrict__ vcol) {
    __shared__ float sc0, sr0;
    if (threadIdx.x == 0) { sc0 = 0.f; sr0 = 0.f; }
    __syncthreads();

    const int lane = threadIdx.x & 15;
    const unsigned hm = 0xFFFFu << (threadIdx.x & 16);
    const int t = blockIdx.x * 16 + (threadIdx.x >> 4);

    const float* nrow = nhots + (size_t)t * N_RELS;
    int cand = 64;
    if (nrow[lane]      != 0.f) cand = lane;
    if (nrow[16 + lane] != 0.f) cand = 16 + lane;
    if (nrow[32 + lane] != 0.f) cand = 32 + lane;
    if (lane < 2 && nrow[48 + lane] != 0.f) cand = 48 + lane;
    #pragma unroll
    for (int off = 8; off; off >>= 1)
        cand = min(cand, __shfl_xor_sync(hm, cand, off, 16));

    int s = hrow[t];
    int o = vcol[t];
    float l1 = __ldg(&g_S1[cand * RP + lane]);
    float l2 = __ldg(&g_S2[cand * RP + lane]);

    if (lane == 0) {
        g_p[t] = cand;
        atomicAdd(&g_cnt[s], 1);
        atomicAdd(&sc0, l1);                   // r=0 hot row
        atomicAdd(&sr0, l2);
    } else {
        atomicAdd(&g_colsum[o * lane], l1);    // flat index: collisions correct
        atomicAdd(&g_rowsum[s * lane], l2);
    }
    __syncthreads();
    if (threadIdx.x == 0) {
        atomicAdd(&g_colsum[0], sc0);
        atomicAdd(&g_rowsum[0], sr0);
    }
}

// ---------------- exclusive scan of counts (single block) -------------------
__global__ void k_scan() {
    __shared__ int wsum[32];
    __shared__ int s_carry;
    int tid = threadIdx.x, lane = tid & 31, wid = tid >> 5;
    if (tid == 0) s_carry = 0;
    __syncthreads();
    for (int base = 0; base < N_NODES; base += 1024) {
        int i = base + tid;
        int v = (i < N_NODES) ? g_cnt[i] : 0;
        int x = v;
        #pragma unroll
        for (int off = 1; off < 32; off <<= 1) {
            int y = __shfl_up_sync(0xffffffffu, x, off);
            if (lane >= off) x += y;
        }
        if (lane == 31) wsum[wid] = x;
        __syncthreads();
        if (wid == 0) {
            int w = wsum[lane];
            int xx = w;
            #pragma unroll
            for (int off = 1; off < 32; off <<= 1) {
                int y = __shfl_up_sync(0xffffffffu, xx, off);
                if (lane >= off) xx += y;
            }
            wsum[lane] = xx;
        }
        __syncthreads();
        int excl = x - v + (wid ? wsum[wid - 1] : 0) + s_carry;
        if (i < N_NODES) { g_start[i] = excl; g_cur[i] = excl; }
        __syncthreads();
        if (tid == 0) s_carry += wsum[31];
        __syncthreads();
    }
    if (threadIdx.x == 0) g_start[N_NODES] = s_carry;
}

// ---------------- fill CSR-by-s ---------------------------------------------
__global__ void k_fill(const int* __restrict__ hrow) {
    int t = blockIdx.x * blockDim.x + threadIdx.x;
    if (t < NT) {
        int pos = atomicAdd(&g_cur[hrow[t]], 1);
        g_idx[pos] = t;
    }
}

// ---------------- layer-1 gather: h[s] = relu(b1 + sum) ---------------------
// Half-warp per s-node; lane doubles as r (for normalization) and j (emb).
__global__ void k_h(const int* __restrict__ vcol, const float* __restrict__ w1,
                    const float* __restrict__ bias1) {
    const int lane = threadIdx.x & 15;
    const unsigned hm = 0xFFFFu << (threadIdx.x & 16);
    const int s = blockIdx.x * 16 + (threadIdx.x >> 4);   // exact: 3125 blocks

    int b0 = g_start[s], b1e = g_start[s + 1];
    float acc = 0.f;
    for (int i = b0; i < b1e; i++) {
        int t = g_idx[i];
        int o = __ldg(&vcol[t]);
        int p = __ldg(&g_p[t]);
        float cs = g_colsum[o * lane];                     // lane == r
        float ln = __ldg(&g_S1[p * RP + lane]) / fmaxf(cs, EPSV);
        #pragma unroll
        for (int rr = 0; rr < 16; rr++) {
            float w = __shfl_sync(hm, ln, rr, 16);
            acc = fmaf(w, w1[(size_t)(o * rr) * EMB + lane], acc);
        }
    }
    g_h[s * EMB + lane] = fmaxf(acc + __ldg(&bias1[lane]), 0.f);
}

// ---------------- layer-2 gather + fused logits scatter ---------------------
// Half-warp per s. t-loop builds u_r[j] = sum_t lat2n(t,r)*h[o_t][j] in regs;
// epilogue: 75 (r,c-pair) tasks over 16 lanes, each one red.v2 into logits.
__global__ void k_sc(const int* __restrict__ vcol, const float* __restrict__ w2,
                     float* __restrict__ logits) {
    __shared__ float sW2[RP * 161];              // [r'][j*10+c], stride 161
    __shared__ float u_sh[16][16 * 17];          // [halfwarp][r*17+j]
    __shared__ float sred[EMB];
    for (int i = threadIdx.x; i < RP * EMB * N_CLASSES; i += blockDim.x) {
        int r = i / (EMB * N_CLASSES);
        sW2[r * 161 + (i - r * (EMB * N_CLASSES))] = w2[i];
    }
    if (threadIdx.x < EMB) sred[threadIdx.x] = 0.f;
    __syncthreads();

    const int lane = threadIdx.x & 15;
    const int hwid = threadIdx.x >> 4;
    const unsigned hm = 0xFFFFu << (threadIdx.x & 16);
    const int s = blockIdx.x * 16 + hwid;        // exact: 3125 blocks

    float rs = g_rowsum[s * lane];               // lane == r (lane0 -> idx 0)
    float invr = (lane == 0) ? 1.f : 1.f / fmaxf(rs, EPSV);

    float u[16];
    #pragma unroll
    for (int r = 1; r < 16; r++) u[r] = 0.f;
    float part = 0.f;                            // r=0 bulk (unnormalized)

    int b0 = g_start[s], b1e = g_start[s + 1];
    for (int i = b0; i < b1e; i++) {
        int t = g_idx[i];
        int o = __ldg(&vcol[t]);
        int p = __ldg(&g_p[t]);
        float hv = g_h[o * EMB + lane];          // lane == j here
        float s2 = __ldg(&g_S2[p * RP + lane]) * invr;
        part = fmaf(__shfl_sync(hm, s2, 0, 16), hv, part);
        #pragma unroll
        for (int r = 1; r < 16; r++)
            u[r] = fmaf(__shfl_sync(hm, s2, r, 16), hv, u[r]);
    }
    #pragma unroll
    for (int r = 1; r < 16; r++) u_sh[hwid][r * 17 + lane] = u[r];
    __syncwarp(hm);

    #pragma unroll
    for (int iter = 0; iter < 5; iter++) {
        int task = iter * 16 + lane;             // 75 tasks: (r-1)*5 + k
        if (task < 75) {
            int r = task / 5 + 1;
            int k = task - (r - 1) * 5;
            int v = s * r;
            int rp = v / N_NODES;
            int node = v - rp * N_NODES;
            const float* wr = &sW2[rp * 161];
            float a = 0.f, b = 0.f;
            #pragma unroll
            for (int j = 0; j < 16; j++) {
                float uj = u_sh[hwid][r * 17 + j];
                a = fmaf(uj, wr[j * N_CLASSES + 2 * k], a);
                b = fmaf(uj, wr[j * N_CLASSES + 2 * k + 1], b);
            }
            float* dst = logits + (size_t)node * N_CLASSES + 2 * k;  // 8B aligned
            asm volatile("red.global.add.v2.f32 [%0], {%1, %2};"
                         :: "l"(dst), "f"(a), "f"(b) : "memory");
        }
    }

    atomicAdd(&sred[lane], part);
    __syncthreads();
    if (threadIdx.x < EMB) atomicAdd(&g_row0vec[threadIdx.x], sred[threadIdx.x]);
}

// ---------------- epilogue: r=0 contribution to logits[0] -------------------
__global__ void k_finish(const float* __restrict__ w2, float* __restrict__ logits) {
    if (threadIdx.x < N_CLASSES) {
        float denom = fmaxf(g_rowsum[0], EPSV);
        float acc = 0.f;
        #pragma unroll
        for (int j = 0; j < EMB; j++)
            acc = fmaf(w2[j * N_CLASSES + threadIdx.x], g_row0vec[j] / denom, acc);
        atomicAdd(&logits[threadIdx.x], acc);
    }
}

// ---------------- launch -----------------------------------------------------
extern "C" void kernel_launch(void* const* d_in, const int* in_sizes, int n_in,
                              void* d_out, int out_size) {
    const float* nhots    = (const float*)d_in[0];
    const int*   hrow     = (const int*)  d_in[1];   // s[t]
    // d_in[2]=hcol, d_in[3]=vrow are derivable (o*r, s*r) -> unused
    const int*   vcol     = (const int*)  d_in[4];   // o[t]
    const float* Wl1      = (const float*)d_in[5];
    const float* bl1      = (const float*)d_in[6];
    const float* Wl2      = (const float*)d_in[7];
    const float* bl2      = (const float*)d_in[8];
    const float* weights1 = (const float*)d_in[9];
    const float* bias1    = (const float*)d_in[10];
    const float* weights2 = (const float*)d_in[11];
    const float* bias2    = (const float*)d_in[12];
    float* out = (float*)d_out;

    k_init<<<1024, 256>>>(bias2, out);
    k_soft<<<1, 512>>>(Wl1, bl1, Wl2, bl2);
    k_p<<<NT / 16, 256>>>(nhots, hrow, vcol);          // 18750 blocks exact
    k_scan<<<1, 1024>>>();
    k_fill<<<(NT + 255) / 256, 256>>>(hrow);
    k_h<<<N_NODES / 16, 256>>>(vcol, weights1, bias1); // 3125 blocks exact
    k_sc<<<N_NODES / 16, 256>>>(vcol, weights2, out);
    k_finish<<<1, 32>>>(weights2, out);
}

// round 15
// speedup vs baseline: 2.0573x; 1.1410x over previous
#include <cuda_runtime.h>
#include <cstdint>

#define N_NODES 50000
#define N_RELS  50
#define N_CLASSES 10
#define EMB     16
#define RP      16
#define NT      300000
#define NRP     (N_NODES * RP)      // 800000
#define EPSV    1e-6f

#define SCAN_BLOCKS 196             // 196*256 = 50176 >= N_NODES

// ---------------- scratch (static device globals) ---------------------------
__device__ float g_colsum[NRP];               // 3.2 MB (flat o*r segment sums)
__device__ float g_rowsum[NRP];               // 3.2 MB (flat s*r segment sums)
__device__ float g_h[N_NODES * EMB];          // 3.2 MB
__device__ float g_row0vec[EMB];              // unnormalized h2[0] (r=0 bulk)
__device__ float g_S1[N_RELS * RP];           // softmax(Wl1[p]+bl1) per relation
__device__ float g_S2[N_RELS * RP];
__device__ int   g_p[NT];                     // relation id per triple
__device__ int   g_idx[NT];                   // CSR-by-s triple list
__device__ int   g_cnt[N_NODES];
__device__ int   g_start[N_NODES + 1];
__device__ int   g_cur[N_NODES];
__device__ int   g_bsum[256];                 // per-chunk sums (padded)

// ---------------- init: zero scratch, logits = bias2, softmax tables --------
__global__ void k_init(const float* __restrict__ bias2, float* __restrict__ out,
                       const float* __restrict__ Wl1, const float* __restrict__ bl1,
                       const float* __restrict__ Wl2, const float* __restrict__ bl2) {
    int i = blockIdx.x * blockDim.x + threadIdx.x;
    int stride = gridDim.x * blockDim.x;
    for (int k = i; k < NRP; k += stride) {
        g_colsum[k] = 0.f;
        g_rowsum[k] = 0.f;
        g_h[k] = 0.f;                          // N_NODES*EMB == NRP
    }
    for (int k = i; k < N_NODES; k += stride) g_cnt[k] = 0;
    for (int k = i; k < N_NODES * N_CLASSES; k += stride)
        out[k] = bias2[k % N_CLASSES];
    if (i < EMB) g_row0vec[i] = 0.f;

    // block 0: per-relation softmax tables (both layers), 16 half-warps
    if (blockIdx.x == 0) {
        int lane = threadIdx.x & 15;
        int hw = threadIdx.x >> 4;
        unsigned hm = 0xFFFFu << (threadIdx.x & 16);
        for (int row = hw; row < N_RELS; row += 16) {
            float a1 = Wl1[row * RP + lane] + bl1[lane];
            float a2 = Wl2[row * RP + lane] + bl2[lane];
            float m1 = a1, m2 = a2;
            #pragma unroll
            for (int off = 8; off; off >>= 1) {
                m1 = fmaxf(m1, __shfl_xor_sync(hm, m1, off, 16));
                m2 = fmaxf(m2, __shfl_xor_sync(hm, m2, off, 16));
            }
            float e1 = __expf(a1 - m1), e2 = __expf(a2 - m2);
            float s1 = e1, s2 = e2;
            #pragma unroll
            for (int off = 8; off; off >>= 1) {
                s1 += __shfl_xor_sync(hm, s1, off, 16);
                s2 += __shfl_xor_sync(hm, s2, off, 16);
            }
            g_S1[row * RP + lane] = e1 / s1;
            g_S2[row * RP + lane] = e2 / s2;   // relu(softmax) == softmax
        }
    }
}

// ---------------- find p[t] from one-hot, counts, colsum/rowsum atomics -----
// One half-warp per triple. Exact grid: NT*16/256 = 18750 blocks.
__global__ void k_p(const float* __restrict__ nhots,
                    const int* __restrict__ hrow, const int* __restrict__ vcol) {
    __shared__ float sc0, sr0;
    if (threadIdx.x == 0) { sc0 = 0.f; sr0 = 0.f; }
    __syncthreads();

    const int lane = threadIdx.x & 15;
    const unsigned hm = 0xFFFFu << (threadIdx.x & 16);
    const int t = blockIdx.x * 16 + (threadIdx.x >> 4);

    const float* nrow = nhots + (size_t)t * N_RELS;
    int cand = 64;
    if (nrow[lane]      != 0.f) cand = lane;
    if (nrow[16 + lane] != 0.f) cand = 16 + lane;
    if (nrow[32 + lane] != 0.f) cand = 32 + lane;
    if (lane < 2 && nrow[48 + lane] != 0.f) cand = 48 + lane;
    #pragma unroll
    for (int off = 8; off; off >>= 1)
        cand = min(cand, __shfl_xor_sync(hm, cand, off, 16));

    int s = hrow[t];
    int o = vcol[t];
    float l1 = __ldg(&g_S1[cand * RP + lane]);
    float l2 = __ldg(&g_S2[cand * RP + lane]);

    if (lane == 0) {
        g_p[t] = cand;
        atomicAdd(&g_cnt[s], 1);
        atomicAdd(&sc0, l1);                   // r=0 hot row
        atomicAdd(&sr0, l2);
    } else {
        atomicAdd(&g_colsum[o * lane], l1);    // flat index: collisions correct
        atomicAdd(&g_rowsum[s * lane], l2);
    }
    __syncthreads();
    if (threadIdx.x == 0) {
        atomicAdd(&g_colsum[0], sc0);
        atomicAdd(&g_rowsum[0], sr0);
    }
}

// ---------------- multi-block exclusive scan of g_cnt -----------------------
__device__ __forceinline__ int block_incl_scan256(int v, int* ws) {
    int lane = threadIdx.x & 31, wid = threadIdx.x >> 5;
    int x = v;
    #pragma unroll
    for (int off = 1; off < 32; off <<= 1) {
        int y = __shfl_up_sync(0xffffffffu, x, off);
        if (lane >= off) x += y;
    }
    if (lane == 31) ws[wid] = x;
    __syncthreads();
    if (wid == 0 && lane < 8) {
        int w = ws[lane];
        #pragma unroll
        for (int off = 1; off < 8; off <<= 1) {
            int y = __shfl_up_sync(0x000000FFu, w, off);
            if (lane >= off) w += y;
        }
        ws[lane] = w;
    }
    __syncthreads();
    return x + (wid ? ws[wid - 1] : 0);
}

__global__ void k_scanA() {                    // SCAN_BLOCKS x 256: chunk sums
    __shared__ int ws[8];
    int i = blockIdx.x * 256 + threadIdx.x;
    int v = (i < N_NODES) ? g_cnt[i] : 0;
    int incl = block_incl_scan256(v, ws);
    if (threadIdx.x == 255) g_bsum[blockIdx.x] = incl;
}

__global__ void k_scanB() {                    // 1 x 256: scan chunk sums
    __shared__ int ws[8];
    int tid = threadIdx.x;
    int v = (tid < SCAN_BLOCKS) ? g_bsum[tid] : 0;
    int incl = block_incl_scan256(v, ws);
    g_bsum[tid] = incl - v;                    // exclusive offsets
    if (tid == 255) g_start[N_NODES] = incl;   // total == NT
}

__global__ void k_scanC() {                    // SCAN_BLOCKS x 256: finalize
    __shared__ int ws[8];
    int i = blockIdx.x * 256 + threadIdx.x;
    int v = (i < N_NODES) ? g_cnt[i] : 0;
    int incl = block_incl_scan256(v, ws);
    int excl = incl - v + g_bsum[blockIdx.x];
    if (i < N_NODES) { g_start[i] = excl; g_cur[i] = excl; }
}

// ---------------- fill CSR-by-s ---------------------------------------------
__global__ void k_fill(const int* __restrict__ hrow) {
    int t = blockIdx.x * blockDim.x + threadIdx.x;
    if (t < NT) {
        int pos = atomicAdd(&g_cur[hrow[t]], 1);
        g_idx[pos] = t;
    }
}

// ---------------- layer-1 gather: h[s] = relu(b1 + sum) ---------------------
// Half-warp per s-node; lane doubles as r (for normalization) and j (emb).
__global__ void k_h(const int* __restrict__ vcol, const float* __restrict__ w1,
                    const float* __restrict__ bias1) {
    const int lane = threadIdx.x & 15;
    const unsigned hm = 0xFFFFu << (threadIdx.x & 16);
    const int s = blockIdx.x * 16 + (threadIdx.x >> 4);   // exact: 3125 blocks

    const float w1r0 = __ldg(&w1[lane]);                  // row 0 (o*0), constant
    int b0 = g_start[s], b1e = g_start[s + 1];
    float acc = 0.f;
    for (int i = b0; i < b1e; i++) {
        int t = g_idx[i];
        int o = __ldg(&vcol[t]);
        int p = __ldg(&g_p[t]);
        float cs = g_colsum[o * lane];                     // lane == r
        float ln = __ldg(&g_S1[p * RP + lane]) / fmaxf(cs, EPSV);
        acc = fmaf(__shfl_sync(hm, ln, 0, 16), w1r0, acc);
        #pragma unroll
        for (int rr = 1; rr < 16; rr++) {
            float w = __shfl_sync(hm, ln, rr, 16);
            acc = fmaf(w, w1[(size_t)(o * rr) * EMB + lane], acc);
        }
    }
    g_h[s * EMB + lane] = fmaxf(acc + __ldg(&bias1[lane]), 0.f);
}

// ---------------- layer-2 gather + fused logits scatter ---------------------
// Half-warp per s. t-loop builds u_r[j] = sum_t lat2n(t,r)*h[o_t][j] in regs;
// epilogue: 75 (r,c-pair) tasks over 16 lanes, each one red.v2 into logits.
__global__ void k_sc(const int* __restrict__ vcol, const float* __restrict__ w2,
                     float* __restrict__ logits) {
    __shared__ float sW2[RP * 161];              // [r'][j*10+c], stride 161
    __shared__ float u_sh[16][16 * 17];          // [halfwarp][r*17+j]
    __shared__ float sred[EMB];
    for (int i = threadIdx.x; i < RP * EMB * N_CLASSES; i += blockDim.x) {
        int r = i / (EMB * N_CLASSES);
        sW2[r * 161 + (i - r * (EMB * N_CLASSES))] = w2[i];
    }
    if (threadIdx.x < EMB) sred[threadIdx.x] = 0.f;
    __syncthreads();

    const int lane = threadIdx.x & 15;
    const int hwid = threadIdx.x >> 4;
    const unsigned hm = 0xFFFFu << (threadIdx.x & 16);
    const int s = blockIdx.x * 16 + hwid;        // exact: 3125 blocks

    float rs = g_rowsum[s * lane];               // lane == r (lane0 -> idx 0)
    float invr = (lane == 0) ? 1.f : 1.f / fmaxf(rs, EPSV);

    float u[16];
    #pragma unroll
    for (int r = 1; r < 16; r++) u[r] = 0.f;
    float part = 0.f;                            // r=0 bulk (unnormalized)

    int b0 = g_start[s], b1e = g_start[s + 1];
    for (int i = b0; i < b1e; i++) {
        int t = g_idx[i];
        int o = __ldg(&vcol[t]);
        int p = __ldg(&g_p[t]);
        float hv = g_h[o * EMB + lane];          // lane == j here
        float s2 = __ldg(&g_S2[p * RP + lane]) * invr;
        part = fmaf(__shfl_sync(hm, s2, 0, 16), hv, part);
        #pragma unroll
        for (int r = 1; r < 16; r++)
            u[r] = fmaf(__shfl_sync(hm, s2, r, 16), hv, u[r]);
    }
    #pragma unroll
    for (int r = 1; r < 16; r++) u_sh[hwid][r * 17 + lane] = u[r];
    __syncwarp(hm);

    #pragma unroll
    for (int iter = 0; iter < 5; iter++) {
        int task = iter * 16 + lane;             // 75 tasks: (r-1)*5 + k
        if (task < 75) {
            int r = task / 5 + 1;
            int k = task - (r - 1) * 5;
            int v = s * r;
            int rp = v / N_NODES;
            int node = v - rp * N_NODES;
            const float* wr = &sW2[rp * 161];
            float a = 0.f, b = 0.f;
            #pragma unroll
            for (int j = 0; j < 16; j++) {
                float uj = u_sh[hwid][r * 17 + j];
                a = fmaf(uj, wr[j * N_CLASSES + 2 * k], a);
                b = fmaf(uj, wr[j * N_CLASSES + 2 * k + 1], b);
            }
            float* dst = logits + (size_t)node * N_CLASSES + 2 * k;  // 8B aligned
            asm volatile("red.global.add.v2.f32 [%0], {%1, %2};"
                         :: "l"(dst), "f"(a), "f"(b) : "memory");
        }
    }

    atomicAdd(&sred[lane], part);
    __syncthreads();
    if (threadIdx.x < EMB) atomicAdd(&g_row0vec[threadIdx.x], sred[threadIdx.x]);
}

// ---------------- epilogue: r=0 contribution to logits[0] -------------------
__global__ void k_finish(const float* __restrict__ w2, float* __restrict__ logits) {
    if (threadIdx.x < N_CLASSES) {
        float denom = fmaxf(g_rowsum[0], EPSV);
        float acc = 0.f;
        #pragma unroll
        for (int j = 0; j < EMB; j++)
            acc = fmaf(w2[j * N_CLASSES + threadIdx.x], g_row0vec[j] / denom, acc);
        atomicAdd(&logits[threadIdx.x], acc);
    }
}

// ---------------- launch -----------------------------------------------------
extern "C" void kernel_launch(void* const* d_in, const int* in_sizes, int n_in,
                              void* d_out, int out_size) {
    const float* nhots    = (const float*)d_in[0];
    const int*   hrow     = (const int*)  d_in[1];   // s[t]
    // d_in[2]=hcol, d_in[3]=vrow are derivable (o*r, s*r) -> unused
    const int*   vcol     = (const int*)  d_in[4];   // o[t]
    const float* Wl1      = (const float*)d_in[5];
    const float* bl1      = (const float*)d_in[6];
    const float* Wl2      = (const float*)d_in[7];
    const float* bl2      = (const float*)d_in[8];
    const float* weights1 = (const float*)d_in[9];
    const float* bias1    = (const float*)d_in[10];
    const float* weights2 = (const float*)d_in[11];
    const float* bias2    = (const float*)d_in[12];
    float* out = (float*)d_out;

    k_init<<<1024, 256>>>(bias2, out, Wl1, bl1, Wl2, bl2);
    k_p<<<NT / 16, 256>>>(nhots, hrow, vcol);          // 18750 blocks exact
    k_scanA<<<SCAN_BLOCKS, 256>>>();
    k_scanB<<<1, 256>>>();
    k_scanC<<<SCAN_BLOCKS, 256>>>();
    k_fill<<<(NT + 255) / 256, 256>>>(hrow);
    k_h<<<N_NODES / 16, 256>>>(vcol, weights1, bias1); // 3125 blocks exact
    k_sc<<<N_NODES / 16, 256>>>(vcol, weights2, out);
    k_finish<<<1, 32>>>(weights2, out);
}

// round 16
// speedup vs baseline: 2.5479x; 1.2384x over previous
#include <cuda_runtime.h>
#include <cstdint>

#define N_NODES 50000
#define N_RELS  50
#define N_CLASSES 10
#define EMB     16
#define RP      16
#define NT      300000
#define NRP     (N_NODES * RP)      // 800000
#define NSEG    (2 * N_NODES)       // 100000 (s-counts then o-counts)
#define EPSV    1e-6f

#define SCAN_BLOCKS 196             // 196*512 = 100352 >= NSEG

// ---------------- scratch (static device globals) ---------------------------
__device__ float g_colsum[NRP];               // 3.2 MB (flat o*r segment sums)
__device__ float g_rowsum[NRP];               // 3.2 MB (flat s*r segment sums)
__device__ float g_h[N_NODES * EMB];          // 3.2 MB
__device__ float g_row0vec[EMB];              // unnormalized h2[0] (r=0 bulk)
__device__ float g_S1[N_RELS * RP];           // softmax(Wl1[p]+bl1) per relation
__device__ float g_S2[N_RELS * RP];
__device__ int   g_p[NT];                     // relation id per triple
__device__ int   g_idx[2 * NT];               // [0,NT): CSR-by-s  [NT,2NT): CSR-by-o
__device__ int   g_cnt[NSEG];
__device__ int   g_start[NSEG + 1];
__device__ int   g_cur[NSEG];
__device__ int   g_bsum[256];

// ---------------- init: zero scratch, logits = bias2, softmax tables --------
__global__ void k_init(const float* __restrict__ bias2, float* __restrict__ out,
                       const float* __restrict__ Wl1, const float* __restrict__ bl1,
                       const float* __restrict__ Wl2, const float* __restrict__ bl2) {
    int i = blockIdx.x * blockDim.x + threadIdx.x;
    int stride = gridDim.x * blockDim.x;
    float4 z4 = make_float4(0.f, 0.f, 0.f, 0.f);
    float4* cs4 = (float4*)g_colsum;
    float4* rs4 = (float4*)g_rowsum;
    float4* h4  = (float4*)g_h;
    for (int k = i; k < NRP / 4; k += stride) {
        cs4[k] = z4; rs4[k] = z4; h4[k] = z4;
    }
    for (int k = i; k < NSEG; k += stride) g_cnt[k] = 0;
    for (int k = i; k < N_NODES * N_CLASSES; k += stride)
        out[k] = bias2[k % N_CLASSES];
    if (i < EMB) g_row0vec[i] = 0.f;

    // block 0: per-relation softmax tables (both layers), 16 half-warps
    if (blockIdx.x == 0) {
        int lane = threadIdx.x & 15;
        int hw = threadIdx.x >> 4;
        unsigned hm = 0xFFFFu << (threadIdx.x & 16);
        for (int row = hw; row < N_RELS; row += 16) {
            float a1 = Wl1[row * RP + lane] + bl1[lane];
            float a2 = Wl2[row * RP + lane] + bl2[lane];
            float m1 = a1, m2 = a2;
            #pragma unroll
            for (int off = 8; off; off >>= 1) {
                m1 = fmaxf(m1, __shfl_xor_sync(hm, m1, off, 16));
                m2 = fmaxf(m2, __shfl_xor_sync(hm, m2, off, 16));
            }
            float e1 = __expf(a1 - m1), e2 = __expf(a2 - m2);
            float s1 = e1, s2 = e2;
            #pragma unroll
            for (int off = 8; off; off >>= 1) {
                s1 += __shfl_xor_sync(hm, s1, off, 16);
                s2 += __shfl_xor_sync(hm, s2, off, 16);
            }
            g_S1[row * RP + lane] = e1 / s1;
            g_S2[row * RP + lane] = e2 / s2;   // relu(softmax) == softmax
        }
    }
}

// ---------------- find p[t] from one-hot + counts (2 atomics / triple) ------
// One half-warp per triple. Exact grid: NT*16/256 = 18750 blocks.
__global__ void k_p(const float* __restrict__ nhots,
                    const int* __restrict__ hrow, const int* __restrict__ vcol) {
    const int lane = threadIdx.x & 15;
    const unsigned hm = 0xFFFFu << (threadIdx.x & 16);
    const int t = blockIdx.x * 16 + (threadIdx.x >> 4);

    const float* nrow = nhots + (size_t)t * N_RELS;
    int cand = 64;
    if (nrow[lane]      != 0.f) cand = lane;
    if (nrow[16 + lane] != 0.f) cand = 16 + lane;
    if (nrow[32 + lane] != 0.f) cand = 32 + lane;
    if (lane < 2 && nrow[48 + lane] != 0.f) cand = 48 + lane;
    #pragma unroll
    for (int off = 8; off; off >>= 1)
        cand = min(cand, __shfl_xor_sync(hm, cand, off, 16));

    if (lane == 0) {
        g_p[t] = cand;
        atomicAdd(&g_cnt[hrow[t]], 1);                 // s-count
        atomicAdd(&g_cnt[N_NODES + vcol[t]], 1);       // o-count
    }
}

// ---------------- multi-block exclusive scan of g_cnt[NSEG] -----------------
__device__ __forceinline__ int bscan512(int v, int* ws) {
    int lane = threadIdx.x & 31, wid = threadIdx.x >> 5;   // 16 warps
    int x = v;
    #pragma unroll
    for (int off = 1; off < 32; off <<= 1) {
        int y = __shfl_up_sync(0xffffffffu, x, off);
        if (lane >= off) x += y;
    }
    if (lane == 31) ws[wid] = x;
    __syncthreads();
    if (wid == 0 && lane < 16) {
        int w = ws[lane];
        #pragma unroll
        for (int off = 1; off < 16; off <<= 1) {
            int y = __shfl_up_sync(0x0000FFFFu, w, off);
            if (lane >= off) w += y;
        }
        ws[lane] = w;
    }
    __syncthreads();
    return x + (wid ? ws[wid - 1] : 0);
}

__global__ void k_scanA() {                    // SCAN_BLOCKS x 512: chunk sums
    __shared__ int ws[16];
    int i = blockIdx.x * 512 + threadIdx.x;
    int v = (i < NSEG) ? g_cnt[i] : 0;
    int incl = bscan512(v, ws);
    if (threadIdx.x == 511) g_bsum[blockIdx.x] = incl;
}

__global__ void k_scanB() {                    // 1 x 512: scan chunk sums
    __shared__ int ws[16];
    int tid = threadIdx.x;
    int v = (tid < SCAN_BLOCKS) ? g_bsum[tid] : 0;
    int incl = bscan512(v, ws);
    if (tid < SCAN_BLOCKS) g_bsum[tid] = incl - v;       // exclusive offsets
    if (tid == 511) g_start[NSEG] = incl;                 // total == 2*NT
}

__global__ void k_scanC() {                    // SCAN_BLOCKS x 512: finalize
    __shared__ int ws[16];
    int i = blockIdx.x * 512 + threadIdx.x;
    int v = (i < NSEG) ? g_cnt[i] : 0;
    int incl = bscan512(v, ws);
    int excl = incl - v + g_bsum[blockIdx.x];
    if (i < NSEG) { g_start[i] = excl; g_cur[i] = excl; }
}

// ---------------- fill both CSRs --------------------------------------------
__global__ void k_fill(const int* __restrict__ hrow, const int* __restrict__ vcol) {
    int t = blockIdx.x * blockDim.x + threadIdx.x;
    if (t < NT) {
        int ps = atomicAdd(&g_cur[hrow[t]], 1);
        g_idx[ps] = t;
        int po = atomicAdd(&g_cur[N_NODES + vcol[t]], 1);
        g_idx[po] = t;
    }
}

// ---------------- colsum + rowsum via per-node gather -----------------------
// 100000 tasks, half-warp each. task<N: rowsum over CSR-s (S2);
// task>=N: colsum over CSR-o (S1). 15 atomics per non-empty node.
__global__ void k_cs() {
    __shared__ float sc0, sr0;
    if (threadIdx.x == 0) { sc0 = 0.f; sr0 = 0.f; }
    __syncthreads();

    const int lane = threadIdx.x & 15;
    const unsigned hm = 0xFFFFu << (threadIdx.x & 16);
    const int task = blockIdx.x * 32 + (threadIdx.x >> 4);  // 3125 blocks x 512

    int b0 = g_start[task], b1 = g_start[task + 1];
    bool isS = task < N_NODES;
    const float* S = isS ? g_S2 : g_S1;
    float acc = 0.f;
    for (int i = b0; i < b1; i++) {
        int p = __ldg(&g_p[g_idx[i]]);
        acc += __ldg(&S[p * RP + lane]);
    }
    int node = isS ? task : task - N_NODES;
    if (b0 < b1) {
        if (node == 0) {
            #pragma unroll
            for (int off = 8; off; off >>= 1)
                acc += __shfl_xor_sync(hm, acc, off, 16);
            if (lane == 0) atomicAdd(isS ? &sr0 : &sc0, acc);
        } else if (lane == 0) {
            atomicAdd(isS ? &sr0 : &sc0, acc);            // r=0 hot row
        } else {
            atomicAdd((isS ? g_rowsum : g_colsum) + node * lane, acc);
        }
    }
    __syncthreads();
    if (threadIdx.x == 0) {
        atomicAdd(&g_rowsum[0], sr0);
        atomicAdd(&g_colsum[0], sc0);
    }
}

// ---------------- layer-1, per-o: w1 rows & colsum loaded ONCE per o --------
// Half-warp per o; wreg[rr] cached in registers; h[s] += contribution via
// red.v4 (4 lanes x 16B per triple).
__global__ void k_h(const int* __restrict__ hrow, const float* __restrict__ w1) {
    const int lane = threadIdx.x & 15;
    const unsigned hm = 0xFFFFu << (threadIdx.x & 16);
    const int o = blockIdx.x * 16 + (threadIdx.x >> 4);   // exact: 3125 blocks

    int b0 = g_start[N_NODES + o], b1 = g_start[N_NODES + o + 1];
    if (b0 == b1) return;

    float wreg[16];
    wreg[0] = __ldg(&w1[lane]);                            // row 0 (o*0)
    #pragma unroll
    for (int rr = 1; rr < 16; rr++)
        wreg[rr] = __ldg(&w1[(size_t)(o * rr) * EMB + lane]);
    float csinv = 1.f / fmaxf(g_colsum[o * lane], EPSV);   // lane == r

    for (int i = b0; i < b1; i++) {
        int t = g_idx[i];
        int p = __ldg(&g_p[t]);
        int s = __ldg(&hrow[t]);
        float v = __ldg(&g_S1[p * RP + lane]) * csinv;
        float acc = 0.f;
        #pragma unroll
        for (int rr = 0; rr < 16; rr++)
            acc = fmaf(__shfl_sync(hm, v, rr, 16), wreg[rr], acc);
        // lanes 0..3 gather 4 consecutive j's each, one red.v4 apiece
        int base = 4 * (lane & 3);
        float a0 = __shfl_sync(hm, acc, base + 0, 16);
        float a1 = __shfl_sync(hm, acc, base + 1, 16);
        float a2 = __shfl_sync(hm, acc, base + 2, 16);
        float a3 = __shfl_sync(hm, acc, base + 3, 16);
        if (lane < 4) {
            float* dst = &g_h[s * EMB + 4 * lane];         // 16B aligned
            asm volatile("red.global.add.v4.f32 [%0], {%1, %2, %3, %4};"
                         :: "l"(dst), "f"(a0), "f"(a1), "f"(a2), "f"(a3)
                         : "memory");
        }
    }
}

// ---------------- h post: relu(h + bias1), vectorized -----------------------
__global__ void k_hpost(const float* __restrict__ bias1) {
    float4* h4 = (float4*)g_h;
    const float4* b4 = (const float4*)bias1;
    int i = blockIdx.x * blockDim.x + threadIdx.x;
    int stride = gridDim.x * blockDim.x;
    for (int k = i; k < N_NODES * 4; k += stride) {
        float4 v = h4[k];
        float4 b = b4[k & 3];
        v.x = fmaxf(v.x + b.x, 0.f);
        v.y = fmaxf(v.y + b.y, 0.f);
        v.z = fmaxf(v.z + b.z, 0.f);
        v.w = fmaxf(v.w + b.w, 0.f);
        h4[k] = v;
    }
}

// ---------------- layer-2 gather + fused logits scatter ---------------------
// Half-warp per s. t-loop builds u_r[j] in regs; epilogue: 75 (r,c-pair)
// tasks over 16 lanes, each one red.v2 into logits.
__global__ void k_sc(const int* __restrict__ vcol, const float* __restrict__ w2,
                     float* __restrict__ logits) {
    __shared__ float sW2[RP * 161];              // [r'][j*10+c], stride 161
    __shared__ float u_sh[16][16 * 17];          // [halfwarp][r*17+j]
    __shared__ float sred[EMB];
    for (int i = threadIdx.x; i < RP * EMB * N_CLASSES; i += blockDim.x) {
        int r = i / (EMB * N_CLASSES);
        sW2[r * 161 + (i - r * (EMB * N_CLASSES))] = w2[i];
    }
    if (threadIdx.x < EMB) sred[threadIdx.x] = 0.f;
    __syncthreads();

    const int lane = threadIdx.x & 15;
    const int hwid = threadIdx.x >> 4;
    const unsigned hm = 0xFFFFu << (threadIdx.x & 16);
    const int s = blockIdx.x * 16 + hwid;        // exact: 3125 blocks

    float rs = g_rowsum[s * lane];               // lane == r (lane0 -> idx 0)
    float invr = (lane == 0) ? 1.f : 1.f / fmaxf(rs, EPSV);

    float u[16];
    #pragma unroll
    for (int r = 1; r < 16; r++) u[r] = 0.f;
    float part = 0.f;                            // r=0 bulk (unnormalized)

    int b0 = g_start[s], b1e = g_start[s + 1];
    for (int i = b0; i < b1e; i++) {
        int t = g_idx[i];
        int o = __ldg(&vcol[t]);
        int p = __ldg(&g_p[t]);
        float hv = g_h[o * EMB + lane];          // lane == j here
        float s2 = __ldg(&g_S2[p * RP + lane]) * invr;
        part = fmaf(__shfl_sync(hm, s2, 0, 16), hv, part);
        #pragma unroll
        for (int r = 1; r < 16; r++)
            u[r] = fmaf(__shfl_sync(hm, s2, r, 16), hv, u[r]);
    }
    #pragma unroll
    for (int r = 1; r < 16; r++) u_sh[hwid][r * 17 + lane] = u[r];
    __syncwarp(hm);

    #pragma unroll
    for (int iter = 0; iter < 5; iter++) {
        int task = iter * 16 + lane;             // 75 tasks: (r-1)*5 + k
        if (task < 75) {
            int r = task / 5 + 1;
            int k = task - (r - 1) * 5;
            int v = s * r;
            int rp = v / N_NODES;
            int node = v - rp * N_NODES;
            const float* wr = &sW2[rp * 161];
            float a = 0.f, b = 0.f;
            #pragma unroll
            for (int j = 0; j < 16; j++) {
                float uj = u_sh[hwid][r * 17 + j];
                a = fmaf(uj, wr[j * N_CLASSES + 2 * k], a);
                b = fmaf(uj, wr[j * N_CLASSES + 2 * k + 1], b);
            }
            float* dst = logits + (size_t)node * N_CLASSES + 2 * k;  // 8B aligned
            asm volatile("red.global.add.v2.f32 [%0], {%1, %2};"
                         :: "l"(dst), "f"(a), "f"(b) : "memory");
        }
    }

    atomicAdd(&sred[lane], part);
    __syncthreads();
    if (threadIdx.x < EMB) atomicAdd(&g_row0vec[threadIdx.x], sred[threadIdx.x]);
}

// ---------------- epilogue: r=0 contribution to logits[0] -------------------
__global__ void k_finish(const float* __restrict__ w2, float* __restrict__ logits) {
    if (threadIdx.x < N_CLASSES) {
        float denom = fmaxf(g_rowsum[0], EPSV);
        float acc = 0.f;
        #pragma unroll
        for (int j = 0; j < EMB; j++)
            acc = fmaf(w2[j * N_CLASSES + threadIdx.x], g_row0vec[j] / denom, acc);
        atomicAdd(&logits[threadIdx.x], acc);
    }
}

// ---------------- launch -----------------------------------------------------
extern "C" void kernel_launch(void* const* d_in, const int* in_sizes, int n_in,
                              void* d_out, int out_size) {
    const float* nhots    = (const float*)d_in[0];
    const int*   hrow     = (const int*)  d_in[1];   // s[t]
    // d_in[2]=hcol, d_in[3]=vrow are derivable (o*r, s*r) -> unused
    const int*   vcol     = (const int*)  d_in[4];   // o[t]
    const float* Wl1      = (const float*)d_in[5];
    const float* bl1      = (const float*)d_in[6];
    const float* Wl2      = (const float*)d_in[7];
    const float* bl2      = (const float*)d_in[8];
    const float* weights1 = (const float*)d_in[9];
    const float* bias1    = (const float*)d_in[10];
    const float* weights2 = (const float*)d_in[11];
    const float* bias2    = (const float*)d_in[12];
    float* out = (float*)d_out;

    k_init<<<1024, 256>>>(bias2, out, Wl1, bl1, Wl2, bl2);
    k_p<<<NT / 16, 256>>>(nhots, hrow, vcol);            // 18750 blocks exact
    k_scanA<<<SCAN_BLOCKS, 512>>>();
    k_scanB<<<1, 512>>>();
    k_scanC<<<SCAN_BLOCKS, 512>>>();
    k_fill<<<(NT + 255) / 256, 256>>>(hrow, vcol);
    k_cs<<<NSEG / 32, 512>>>();                          // 3125 blocks exact
    k_h<<<N_NODES / 16, 256>>>(hrow, weights1);          // 3125 blocks exact
    k_hpost<<<512, 256>>>(bias1);
    k_sc<<<N_NODES / 16, 256>>>(vcol, weights2, out);
    k_finish<<<1, 32>>>(weights2, out);
}

// round 17
// speedup vs baseline: 2.7514x; 1.0799x over previous
#include <cuda_runtime.h>
#include <cstdint>

#define N_NODES 50000
#define N_RELS  50
#define N_CLASSES 10
#define EMB     16
#define RP      16
#define NT      300000
#define NRP     (N_NODES * RP)      // 800000
#define NSEG    (2 * N_NODES)       // 100000 (s-counts then o-counts)
#define EPSV    1e-6f

#define SCAN_BLOCKS 196             // 196*512 = 100352 >= NSEG
#define NODE_MASK 0x1FFFF           // 17 bits >= 50000

// ---------------- scratch (static device globals) ---------------------------
__device__ float g_colsum[NRP];               // 3.2 MB (flat o*r segment sums)
__device__ float g_rowsum[NRP];               // 3.2 MB (flat s*r segment sums)
__device__ float g_h[N_NODES * EMB];          // 3.2 MB (raw sums; bias/relu fused)
__device__ float g_row0vec[EMB];              // unnormalized h2[0] (r=0 bulk)
__device__ float g_S1[N_RELS * RP];           // softmax(Wl1[p]+bl1) per relation
__device__ float g_S2[N_RELS * RP];
__device__ int   g_p[NT];                     // relation id per triple
__device__ int   g_idx[2 * NT];               // packed: node(17b) | p<<17
                                              // [0,NT): CSR-by-s holds (o,p)
                                              // [NT,2NT): CSR-by-o holds (s,p)
__device__ int   g_cnt[NSEG];
__device__ int   g_start[NSEG + 1];
__device__ int   g_cur[NSEG];
__device__ int   g_bsum[256];

// ---------------- init: zero scratch, logits = bias2, softmax tables --------
__global__ void k_init(const float* __restrict__ bias2, float* __restrict__ out,
                       const float* __restrict__ Wl1, const float* __restrict__ bl1,
                       const float* __restrict__ Wl2, const float* __restrict__ bl2) {
    int i = blockIdx.x * blockDim.x + threadIdx.x;
    int stride = gridDim.x * blockDim.x;
    float4 z4 = make_float4(0.f, 0.f, 0.f, 0.f);
    float4* cs4 = (float4*)g_colsum;
    float4* rs4 = (float4*)g_rowsum;
    float4* h4  = (float4*)g_h;
    for (int k = i; k < NRP / 4; k += stride) {
        cs4[k] = z4; rs4[k] = z4; h4[k] = z4;
    }
    for (int k = i; k < NSEG; k += stride) g_cnt[k] = 0;
    for (int k = i; k < N_NODES * N_CLASSES; k += stride)
        out[k] = bias2[k % N_CLASSES];
    if (i < EMB) g_row0vec[i] = 0.f;

    // block 0: per-relation softmax tables (both layers), 16 half-warps
    if (blockIdx.x == 0) {
        int lane = threadIdx.x & 15;
        int hw = threadIdx.x >> 4;
        unsigned hm = 0xFFFFu << (threadIdx.x & 16);
        for (int row = hw; row < N_RELS; row += 16) {
            float a1 = Wl1[row * RP + lane] + bl1[lane];
            float a2 = Wl2[row * RP + lane] + bl2[lane];
            float m1 = a1, m2 = a2;
            #pragma unroll
            for (int off = 8; off; off >>= 1) {
                m1 = fmaxf(m1, __shfl_xor_sync(hm, m1, off, 16));
                m2 = fmaxf(m2, __shfl_xor_sync(hm, m2, off, 16));
            }
            float e1 = __expf(a1 - m1), e2 = __expf(a2 - m2);
            float s1 = e1, s2 = e2;
            #pragma unroll
            for (int off = 8; off; off >>= 1) {
                s1 += __shfl_xor_sync(hm, s1, off, 16);
                s2 += __shfl_xor_sync(hm, s2, off, 16);
            }
            g_S1[row * RP + lane] = e1 / s1;
            g_S2[row * RP + lane] = e2 / s2;   // relu(softmax) == softmax
        }
    }
}

// ---------------- find p[t] from one-hot + counts (2 atomics / triple) ------
// One half-warp per triple. Exact grid: NT*16/256 = 18750 blocks.
__global__ void k_p(const float* __restrict__ nhots,
                    const int* __restrict__ hrow, const int* __restrict__ vcol) {
    const int lane = threadIdx.x & 15;
    const unsigned hm = 0xFFFFu << (threadIdx.x & 16);
    const int t = blockIdx.x * 16 + (threadIdx.x >> 4);

    const float* nrow = nhots + (size_t)t * N_RELS;
    int cand = 64;
    if (nrow[lane]      != 0.f) cand = lane;
    if (nrow[16 + lane] != 0.f) cand = 16 + lane;
    if (nrow[32 + lane] != 0.f) cand = 32 + lane;
    if (lane < 2 && nrow[48 + lane] != 0.f) cand = 48 + lane;
    #pragma unroll
    for (int off = 8; off; off >>= 1)
        cand = min(cand, __shfl_xor_sync(hm, cand, off, 16));

    if (lane == 0) {
        g_p[t] = cand;
        atomicAdd(&g_cnt[hrow[t]], 1);                 // s-count
        atomicAdd(&g_cnt[N_NODES + vcol[t]], 1);       // o-count
    }
}

// ---------------- multi-block exclusive scan of g_cnt[NSEG] -----------------
__device__ __forceinline__ int bscan512(int v, int* ws) {
    int lane = threadIdx.x & 31, wid = threadIdx.x >> 5;   // 16 warps
    int x = v;
    #pragma unroll
    for (int off = 1; off < 32; off <<= 1) {
        int y = __shfl_up_sync(0xffffffffu, x, off);
        if (lane >= off) x += y;
    }
    if (lane == 31) ws[wid] = x;
    __syncthreads();
    if (wid == 0 && lane < 16) {
        int w = ws[lane];
        #pragma unroll
        for (int off = 1; off < 16; off <<= 1) {
            int y = __shfl_up_sync(0x0000FFFFu, w, off);
            if (lane >= off) w += y;
        }
        ws[lane] = w;
    }
    __syncthreads();
    return x + (wid ? ws[wid - 1] : 0);
}

__global__ void k_scanA() {                    // SCAN_BLOCKS x 512: chunk sums
    __shared__ int ws[16];
    int i = blockIdx.x * 512 + threadIdx.x;
    int v = (i < NSEG) ? g_cnt[i] : 0;
    int incl = bscan512(v, ws);
    if (threadIdx.x == 511) g_bsum[blockIdx.x] = incl;
}

__global__ void k_scanB() {                    // 1 x 512: scan chunk sums
    __shared__ int ws[16];
    int tid = threadIdx.x;
    int v = (tid < SCAN_BLOCKS) ? g_bsum[tid] : 0;
    int incl = bscan512(v, ws);
    if (tid < SCAN_BLOCKS) g_bsum[tid] = incl - v;       // exclusive offsets
    if (tid == 511) g_start[NSEG] = incl;                 // total == 2*NT
}

__global__ void k_scanC() {                    // SCAN_BLOCKS x 512: finalize
    __shared__ int ws[16];
    int i = blockIdx.x * 512 + threadIdx.x;
    int v = (i < NSEG) ? g_cnt[i] : 0;
    int incl = bscan512(v, ws);
    int excl = incl - v + g_bsum[blockIdx.x];
    if (i < NSEG) { g_start[i] = excl; g_cur[i] = excl; }
}

// ---------------- fill both CSRs with packed (node, p) payloads -------------
// All source reads (hrow, vcol, g_p) coalesced; consumers never deref t again.
__global__ void k_fill(const int* __restrict__ hrow, const int* __restrict__ vcol) {
    int t = blockIdx.x * blockDim.x + threadIdx.x;
    if (t < NT) {
        int p = g_p[t];
        int s = hrow[t];
        int o = vcol[t];
        int ps = atomicAdd(&g_cur[s], 1);
        g_idx[ps] = o | (p << 17);                   // CSR-s entry: (o, p)
        int po = atomicAdd(&g_cur[N_NODES + o], 1);
        g_idx[po] = s | (p << 17);                   // CSR-o entry: (s, p)
    }
}

// ---------------- colsum + rowsum via per-node gather -----------------------
// 100000 tasks, half-warp each. task<N: rowsum over CSR-s (S2);
// task>=N: colsum over CSR-o (S1). Pure coalesced CSR stream + L1 S-table.
__global__ void k_cs() {
    __shared__ float sc0, sr0;
    if (threadIdx.x == 0) { sc0 = 0.f; sr0 = 0.f; }
    __syncthreads();

    const int lane = threadIdx.x & 15;
    const unsigned hm = 0xFFFFu << (threadIdx.x & 16);
    const int task = blockIdx.x * 32 + (threadIdx.x >> 4);  // 3125 blocks x 512

    int b0 = g_start[task], b1 = g_start[task + 1];
    bool isS = task < N_NODES;
    const float* S = isS ? g_S2 : g_S1;
    float acc = 0.f;
    for (int i = b0; i < b1; i++) {
        int p = ((unsigned)__ldg(&g_idx[i])) >> 17;
        acc += __ldg(&S[p * RP + lane]);
    }
    int node = isS ? task : task - N_NODES;
    if (b0 < b1) {
        if (node == 0) {
            #pragma unroll
            for (int off = 8; off; off >>= 1)
                acc += __shfl_xor_sync(hm, acc, off, 16);
            if (lane == 0) atomicAdd(isS ? &sr0 : &sc0, acc);
        } else if (lane == 0) {
            atomicAdd(isS ? &sr0 : &sc0, acc);            // r=0 hot row
        } else {
            atomicAdd((isS ? g_rowsum : g_colsum) + node * lane, acc);
        }
    }
    __syncthreads();
    if (threadIdx.x == 0) {
        atomicAdd(&g_rowsum[0], sr0);
        atomicAdd(&g_colsum[0], sc0);
    }
}

// ---------------- layer-1, per-o: w1 rows & colsum loaded ONCE per o --------
// Half-warp per o; wreg[rr] cached in registers; h[s] += contribution via
// red.v4 (4 lanes x 16B per triple). CSR-o entry already carries (s, p).
__global__ void k_h(const float* __restrict__ w1) {
    const int lane = threadIdx.x & 15;
    const unsigned hm = 0xFFFFu << (threadIdx.x & 16);
    const int o = blockIdx.x * 16 + (threadIdx.x >> 4);   // exact: 3125 blocks

    int b0 = g_start[N_NODES + o], b1 = g_start[N_NODES + o + 1];
    if (b0 == b1) return;

    float wreg[16];
    wreg[0] = __ldg(&w1[lane]);                            // row 0 (o*0)
    #pragma unroll
    for (int rr = 1; rr < 16; rr++)
        wreg[rr] = __ldg(&w1[(size_t)(o * rr) * EMB + lane]);
    float csinv = 1.f / fmaxf(g_colsum[o * lane], EPSV);   // lane == r

    for (int i = b0; i < b1; i++) {
        int e = __ldg(&g_idx[i]);
        int s = e & NODE_MASK;
        int p = ((unsigned)e) >> 17;
        float v = __ldg(&g_S1[p * RP + lane]) * csinv;
        float acc = 0.f;
        #pragma unroll
        for (int rr = 0; rr < 16; rr++)
            acc = fmaf(__shfl_sync(hm, v, rr, 16), wreg[rr], acc);
        // lanes 0..3 gather 4 consecutive j's each, one red.v4 apiece
        int base = 4 * (lane & 3);
        float a0 = __shfl_sync(hm, acc, base + 0, 16);
        float a1 = __shfl_sync(hm, acc, base + 1, 16);
        float a2 = __shfl_sync(hm, acc, base + 2, 16);
        float a3 = __shfl_sync(hm, acc, base + 3, 16);
        if (lane < 4) {
            float* dst = &g_h[s * EMB + 4 * lane];         // 16B aligned
            asm volatile("red.global.add.v4.f32 [%0], {%1, %2, %3, %4};"
                         :: "l"(dst), "f"(a0), "f"(a1), "f"(a2), "f"(a3)
                         : "memory");
        }
    }
}

// ---------------- layer-2 gather + fused logits scatter ---------------------
// Half-warp per s. bias1+relu applied at h-gather time (k_hpost fused away).
// t-loop builds u_r[j] in regs; epilogue: 75 (r,c-pair) tasks over 16 lanes,
// each one red.v2 into logits.
__global__ void k_sc(const float* __restrict__ w2, const float* __restrict__ bias1,
                     float* __restrict__ logits) {
    __shared__ float sW2[RP * 161];              // [r'][j*10+c], stride 161
    __shared__ float u_sh[16][16 * 17];          // [halfwarp][r*17+j]
    __shared__ float sred[EMB];
    for (int i = threadIdx.x; i < RP * EMB * N_CLASSES; i += blockDim.x) {
        int r = i / (EMB * N_CLASSES);
        sW2[r * 161 + (i - r * (EMB * N_CLASSES))] = w2[i];
    }
    if (threadIdx.x < EMB) sred[threadIdx.x] = 0.f;
    __syncthreads();

    const int lane = threadIdx.x & 15;
    const int hwid = threadIdx.x >> 4;
    const unsigned hm = 0xFFFFu << (threadIdx.x & 16);
    const int s = blockIdx.x * 16 + hwid;        // exact: 3125 blocks

    const float b1l = __ldg(&bias1[lane]);       // bias for j == lane
    float rs = g_rowsum[s * lane];               // lane == r (lane0 -> idx 0)
    float invr = (lane == 0) ? 1.f : 1.f / fmaxf(rs, EPSV);

    float u[16];
    #pragma unroll
    for (int r = 1; r < 16; r++) u[r] = 0.f;
    float part = 0.f;                            // r=0 bulk (unnormalized)

    int b0 = g_start[s], b1e = g_start[s + 1];
    for (int i = b0; i < b1e; i++) {
        int e = __ldg(&g_idx[i]);
        int o = e & NODE_MASK;
        int p = ((unsigned)e) >> 17;
        float hv = fmaxf(g_h[o * EMB + lane] + b1l, 0.f);  // relu(h+bias) fused
        float s2 = __ldg(&g_S2[p * RP + lane]) * invr;
        part = fmaf(__shfl_sync(hm, s2, 0, 16), hv, part);
        #pragma unroll
        for (int r = 1; r < 16; r++)
            u[r] = fmaf(__shfl_sync(hm, s2, r, 16), hv, u[r]);
    }

    if (b0 != b1e) {
        #pragma unroll
        for (int r = 1; r < 16; r++) u_sh[hwid][r * 17 + lane] = u[r];
        __syncwarp(hm);

        #pragma unroll
        for (int iter = 0; iter < 5; iter++) {
            int task = iter * 16 + lane;             // 75 tasks: (r-1)*5 + k
            if (task < 75) {
                int r = task / 5 + 1;
                int k = task - (r - 1) * 5;
                int v = s * r;
                int rp = v / N_NODES;
                int node = v - rp * N_NODES;
                const float* wr = &sW2[rp * 161];
                float a = 0.f, b = 0.f;
                #pragma unroll
                for (int j = 0; j < 16; j++) {
                    float uj = u_sh[hwid][r * 17 + j];
                    a = fmaf(uj, wr[j * N_CLASSES + 2 * k], a);
                    b = fmaf(uj, wr[j * N_CLASSES + 2 * k + 1], b);
                }
                float* dst = logits + (size_t)node * N_CLASSES + 2 * k;  // 8B
                asm volatile("red.global.add.v2.f32 [%0], {%1, %2};"
                             :: "l"(dst), "f"(a), "f"(b) : "memory");
            }
        }
    }

    atomicAdd(&sred[lane], part);
    __syncthreads();
    if (threadIdx.x < EMB) atomicAdd(&g_row0vec[threadIdx.x], sred[threadIdx.x]);
}

// ---------------- epilogue: r=0 contribution to logits[0] -------------------
__global__ void k_finish(const float* __restrict__ w2, float* __restrict__ logits) {
    if (threadIdx.x < N_CLASSES) {
        float denom = fmaxf(g_rowsum[0], EPSV);
        float acc = 0.f;
        #pragma unroll
        for (int j = 0; j < EMB; j++)
            acc = fmaf(w2[j * N_CLASSES + threadIdx.x], g_row0vec[j] / denom, acc);
        atomicAdd(&logits[threadIdx.x], acc);
    }
}

// ---------------- launch -----------------------------------------------------
extern "C" void kernel_launch(void* const* d_in, const int* in_sizes, int n_in,
                              void* d_out, int out_size) {
    const float* nhots    = (const float*)d_in[0];
    const int*   hrow     = (const int*)  d_in[1];   // s[t]
    // d_in[2]=hcol, d_in[3]=vrow are derivable (o*r, s*r) -> unused
    const int*   vcol     = (const int*)  d_in[4];   // o[t]
    const float* Wl1      = (const float*)d_in[5];
    const float* bl1      = (const float*)d_in[6];
    const float* Wl2      = (const float*)d_in[7];
    const float* bl2      = (const float*)d_in[8];
    const float* weights1 = (const float*)d_in[9];
    const float* bias1    = (const float*)d_in[10];
    const float* weights2 = (const float*)d_in[11];
    const float* bias2    = (const float*)d_in[12];
    float* out = (float*)d_out;

    k_init<<<1024, 256>>>(bias2, out, Wl1, bl1, Wl2, bl2);
    k_p<<<NT / 16, 256>>>(nhots, hrow, vcol);            // 18750 blocks exact
    k_scanA<<<SCAN_BLOCKS, 512>>>();
    k_scanB<<<1, 512>>>();
    k_scanC<<<SCAN_BLOCKS, 512>>>();
    k_fill<<<(NT + 255) / 256, 256>>>(hrow, vcol);
    k_cs<<<NSEG / 32, 512>>>();                          // 3125 blocks exact
    k_h<<<N_NODES / 16, 256>>>(weights1);                // 3125 blocks exact
    k_sc<<<N_NODES / 16, 256>>>(weights2, bias1, out);
    k_finish<<<1, 32>>>(weights2, out);
}